// round 2
// baseline (speedup 1.0000x reference)
#include <cuda_runtime.h>

#define T_DIM 2048
#define B_DIM 256
#define D_DIM 256
#define G_DIM 32               // 4*H
#define H_DIM 8
#define M_ROWS (T_DIM * B_DIM) // 524288 rows

// 64 MB scratch for precomputed gate pre-activations (x @ W_ih^T + b_ih + b_hh)
__device__ __align__(16) float g_xgb[(size_t)M_ROWS * G_DIM];

// ---------------- packed f32x2 helpers (Blackwell-only, PTX required) ----------------
__device__ __forceinline__ unsigned long long f2pack(float lo, float hi) {
    unsigned long long r;
    asm("mov.b64 %0, {%1,%2};" : "=l"(r) : "f"(lo), "f"(hi));
    return r;
}
__device__ __forceinline__ void f2unpack(unsigned long long v, float& lo, float& hi) {
    asm("mov.b64 {%0,%1}, %2;" : "=f"(lo), "=f"(hi) : "l"(v));
}
__device__ __forceinline__ unsigned long long f2fma(unsigned long long a,
                                                    unsigned long long b,
                                                    unsigned long long c) {
    unsigned long long d;
    asm("fma.rn.f32x2 %0, %1, %2, %3;" : "=l"(d) : "l"(a), "l"(b), "l"(c));
    return d;
}

// ---------------- Kernel 1: gates GEMM ----------------
// g_xgb[r][g] = sum_k x[r][k] * W_ih[g][k] + b_ih[g] + b_hh[g]
// 256 threads, tile = 128 rows x 32 gates. Thread = (gate-pair gt in 0..15, row-group rt in 0..15).
// Rows packed in f32x2: acc[p][q] = (out[r2p][g0+q], out[r2p+1][g0+q]).
#define TILE_R 128
#define KC 32
#define XS_STR 130  // pad (even, for LDS.64) to break STS bank conflicts

__global__ __launch_bounds__(256) void gemm_kernel(
    const float* __restrict__ x, const float* __restrict__ W,
    const float* __restrict__ bih, const float* __restrict__ bhh)
{
    __shared__ __align__(16) float xs[KC * XS_STR];   // [k][row], transposed tile
    __shared__ __align__(16) float ws[KC * G_DIM];    // [k][gate], pair-swizzled

    const int tid = threadIdx.x;
    const long rowBase = (long)blockIdx.x * TILE_R;
    const int gt = tid & 15;   // gate pair id -> gates (2*gt, 2*gt+1)
    const int rt = tid >> 4;   // row group  -> rows rt*8 .. rt*8+7
    const int g0 = gt << 1;

    const float b0 = bih[g0] + bhh[g0];
    const float b1 = bih[g0 + 1] + bhh[g0 + 1];
    unsigned long long acc[4][2];
#pragma unroll
    for (int p = 0; p < 4; p++) {
        acc[p][0] = f2pack(b0, b0);
        acc[p][1] = f2pack(b1, b1);
    }

    for (int kc = 0; kc < D_DIM; kc += KC) {
        // ---- load x tile [128 rows][32 k] transposed into xs[k][row] ----
#pragma unroll
        for (int j = 0; j < 4; j++) {
            int fidx = tid + j * 256;          // 0..1023 float4 slots
            int row = fidx >> 3;               // 0..127
            int kf  = fidx & 7;                // float4 within the 32-wide k chunk
            const float4 v = *reinterpret_cast<const float4*>(
                &x[(rowBase + row) * D_DIM + kc + kf * 4]);
            xs[(kf * 4 + 0) * XS_STR + row] = v.x;
            xs[(kf * 4 + 1) * XS_STR + row] = v.y;
            xs[(kf * 4 + 2) * XS_STR + row] = v.z;
            xs[(kf * 4 + 3) * XS_STR + row] = v.w;
        }
        // ---- load W chunk [32 gates][32 k] into ws[k][gate] (pair-XOR swizzle) ----
        {
            int e = tid * 4;
            int g  = e >> 5;       // 0..31
            int kk = e & 31;       // multiple of 4
            const float4 wv = *reinterpret_cast<const float4*>(&W[g * D_DIM + kc + kk]);
            int gp = g >> 1, gb = g & 1;
            float wvv[4] = {wv.x, wv.y, wv.z, wv.w};
#pragma unroll
            for (int u = 0; u < 4; u++) {
                int k = kk + u;
                ws[k * G_DIM + (((gp ^ (k & 15)) << 1) | gb)] = wvv[u];
            }
        }
        __syncthreads();

#pragma unroll
        for (int k = 0; k < KC; k++) {
            unsigned long long w2 = *reinterpret_cast<const unsigned long long*>(
                &ws[k * G_DIM + ((gt ^ (k & 15)) << 1)]);
            float wl, wh;
            f2unpack(w2, wl, wh);
            unsigned long long wl2 = f2pack(wl, wl);
            unsigned long long wh2 = f2pack(wh, wh);
#pragma unroll
            for (int p = 0; p < 4; p++) {
                unsigned long long xa = *reinterpret_cast<const unsigned long long*>(
                    &xs[k * XS_STR + rt * 8 + 2 * p]);
                acc[p][0] = f2fma(xa, wl2, acc[p][0]);
                acc[p][1] = f2fma(xa, wh2, acc[p][1]);
            }
        }
        __syncthreads();
    }

    // ---- epilogue: repack so each STG.64 covers (g0, g0+1) for one row ----
#pragma unroll
    for (int p = 0; p < 4; p++) {
        long r = rowBase + rt * 8 + 2 * p;
        float a0l, a0h, a1l, a1h;
        f2unpack(acc[p][0], a0l, a0h);
        f2unpack(acc[p][1], a1l, a1h);
        *reinterpret_cast<float2*>(&g_xgb[r * G_DIM + g0])       = make_float2(a0l, a1l);
        *reinterpret_cast<float2*>(&g_xgb[(r + 1) * G_DIM + g0]) = make_float2(a0h, a1h);
    }
}

// ---------------- Kernel 2: reset-segmented LSTM scan + projection ----------------
__device__ __forceinline__ float fast_sigmoid(float v) {
    v = fmaxf(v, -80.0f);                 // avoid inf/inf
    float e = __expf(-v);
    return __fdividef(1.0f, 1.0f + e);
}
__device__ __forceinline__ float fast_tanh(float v) {
    float vc = fminf(fmaxf(v, -20.0f), 20.0f);
    float e = __expf(-2.0f * vc);
    return __fdividef(1.0f - e, 1.0f + e);
}

__global__ __launch_bounds__(256) void scan_kernel(
    const int* __restrict__ reset, const float* __restrict__ Whh,
    const float* __restrict__ Wproj, const float* __restrict__ bproj,
    float* __restrict__ out)
{
    __shared__ float wsh[G_DIM * H_DIM];
    __shared__ float wpsh[H_DIM];
    __shared__ float bpsh;
    const int tid = threadIdx.x;
    if (tid < G_DIM * H_DIM) wsh[tid] = Whh[tid];
    if (tid < H_DIM) wpsh[tid] = Wproj[tid];
    if (tid == 0) bpsh = bproj[0];
    __syncthreads();

    const int gid  = blockIdx.x * 32 + (tid >> 3);  // candidate segment start = (t0, b)
    const int lane = tid & 7;                        // owns hidden element `lane`
    const int t0 = gid >> 8;                         // / B_DIM (256)
    const int b  = gid & 255;

    // A segment starts at t if t==0 or reset[t,b]==1 (state zeroed before step t)
    const bool startp = (t0 == 0) || (reset[gid] != 0);
    if (!startp) return;

    const unsigned mask = 0xFFu << (((tid >> 3) & 3) << 3);  // this 8-lane group

    // Lane j holds W_hh rows {j, j+8, j+16, j+24} (i, f, g, o) in registers
    float wi[8], wf[8], wg[8], wo[8], wp[8];
#pragma unroll
    for (int k = 0; k < 8; k++) {
        wi[k] = wsh[lane * 8 + k];
        wf[k] = wsh[(lane + 8) * 8 + k];
        wg[k] = wsh[(lane + 16) * 8 + k];
        wo[k] = wsh[(lane + 24) * 8 + k];
        wp[k] = wpsh[k];
    }
    const float bp = bpsh;

    float h[8];
#pragma unroll
    for (int k = 0; k < 8; k++) h[k] = 0.0f;
    float c = 0.0f;

    int t = t0;
    while (true) {
        const float* xg = &g_xgb[((long)t * B_DIM + b) * G_DIM];
        float gi = xg[lane];
        float gf = xg[lane + 8];
        float gG = xg[lane + 16];
        float go = xg[lane + 24];
#pragma unroll
        for (int k = 0; k < 8; k++) {
            gi = fmaf(h[k], wi[k], gi);
            gf = fmaf(h[k], wf[k], gf);
            gG = fmaf(h[k], wg[k], gG);
            go = fmaf(h[k], wo[k], go);
        }
        const float iv = fast_sigmoid(gi);
        const float fv = fast_sigmoid(gf);
        const float gv = fast_tanh(gG);
        const float ov = fast_sigmoid(go);
        c = fmaf(fv, c, iv * gv);
        const float hj = ov * fast_tanh(c);

        // broadcast the 8 new hidden values to all lanes of the group
#pragma unroll
        for (int k = 0; k < 8; k++)
            h[k] = __shfl_sync(mask, hj, k, 8);

        if (lane == 0) {
            float v = bp;
#pragma unroll
            for (int k = 0; k < 8; k++) v = fmaf(h[k], wp[k], v);
            out[t * B_DIM + b] = v;
        }

        t++;
        if (t >= T_DIM) break;
        if (reset[t * B_DIM + b] != 0) break;  // next segment handles t
    }
}

// ---------------- launch ----------------
extern "C" void kernel_launch(void* const* d_in, const int* in_sizes, int n_in,
                              void* d_out, int out_size) {
    const float* x      = (const float*)d_in[0];
    const int*   reset  = (const int*)d_in[1];
    const float* W_ih   = (const float*)d_in[2];
    const float* W_hh   = (const float*)d_in[3];
    const float* b_ih   = (const float*)d_in[4];
    const float* b_hh   = (const float*)d_in[5];
    const float* W_proj = (const float*)d_in[6];
    const float* b_proj = (const float*)d_in[7];
    float* out = (float*)d_out;

    gemm_kernel<<<M_ROWS / TILE_R, 256>>>(x, W_ih, b_ih, b_hh);
    scan_kernel<<<M_ROWS / 32, 256>>>(reset, W_hh, W_proj, b_proj, out);
}

// round 8
// speedup vs baseline: 1.4295x; 1.4295x over previous
#include <cuda_runtime.h>
#include <cuda_bf16.h>
#include <cstdint>

#define T_DIM 2048
#define B_DIM 256
#define D_DIM 256
#define G_DIM 32               // 4*H
#define H_DIM 8
#define M_ROWS (T_DIM * B_DIM) // 524288

// 64 MB scratch for gate pre-activations (x @ W_ih^T + b_ih + b_hh)
__device__ __align__(16) float g_xgb[(size_t)M_ROWS * G_DIM];

// ---------------- bf16 split helper: v -> (hi, lo) packed bf16x2 ----------------
__device__ __forceinline__ void split2(float2 v, uint32_t& hi, uint32_t& lo) {
    __nv_bfloat162 h = __floats2bfloat162_rn(v.x, v.y);
    float2 hf = __bfloat1622float2(h);
    __nv_bfloat162 l = __floats2bfloat162_rn(v.x - hf.x, v.y - hf.y);
    hi = *reinterpret_cast<uint32_t*>(&h);
    lo = *reinterpret_cast<uint32_t*>(&l);
}

// mma.sync m16n8k16 row.col f32.bf16.bf16.f32 (base PTX, works on compute_103)
__device__ __forceinline__ void mma16816(float c[4], const uint32_t a[4],
                                         uint32_t b0, uint32_t b1) {
    asm volatile(
        "mma.sync.aligned.m16n8k16.row.col.f32.bf16.bf16.f32 "
        "{%0,%1,%2,%3}, {%4,%5,%6,%7}, {%8,%9}, {%0,%1,%2,%3};"
        : "+f"(c[0]), "+f"(c[1]), "+f"(c[2]), "+f"(c[3])
        : "r"(a[0]), "r"(a[1]), "r"(a[2]), "r"(a[3]), "r"(b0), "r"(b1));
}

// ======================= Kernel 1: gates GEMM on HMMA =======================
// g_xgb[r][g] = sum_k x[r][k]*W[g][k] + b_ih[g] + b_hh[g]
// 3-term bf16 split: D += Ahi*Bhi + Alo*Bhi + Ahi*Blo
// CTA: 128 rows; 8 warps x 16 rows; N=32 (4 n-tiles of 8); K=256 (16 k-steps).
#define TILE_M 128

__global__ __launch_bounds__(256) void gemm_mma(
    const float* __restrict__ x, const float* __restrict__ W,
    const float* __restrict__ bih, const float* __restrict__ bhh)
{
    // B fragments prepacked: [term(hi/lo)][ks][nt][lane*2 + reg]  (uint2 per lane)
    __shared__ __align__(16) uint32_t bfrag[2][16][4][64];
    __shared__ float bs[G_DIM];

    const int tid = threadIdx.x;
    if (tid < G_DIM) bs[tid] = bih[tid] + bhh[tid];

    // ---- prepack W (fp32 -> bf16 hi/lo) into mma B-fragment layout ----
    // B col-major 16x8: b_reg0 -> (k=2*tig,   n=g), (k=2*tig+1, n=g)
    //                   b_reg1 -> (k=2*tig+8, n=g), (k=2*tig+9, n=g)
    // B[k][n] = W[n][k]
    for (int e = tid; e < 4096; e += 256) {
        const int reg = e & 1;
        const int lane = (e >> 1) & 31;
        const int nt  = (e >> 6) & 3;
        const int ks  = e >> 8;
        const int g   = lane >> 2, tig = lane & 3;
        const int n   = nt * 8 + g;
        const int k   = ks * 16 + tig * 2 + reg * 8;
        float2 w = *reinterpret_cast<const float2*>(&W[n * D_DIM + k]);
        uint32_t hp, lp;
        split2(w, hp, lp);
        bfrag[0][ks][nt][lane * 2 + reg] = hp;
        bfrag[1][ks][nt][lane * 2 + reg] = lp;
    }
    __syncthreads();

    const int wid  = tid >> 5;
    const int lane = tid & 31;
    const int g    = lane >> 2;
    const int tig  = lane & 3;
    const long rb  = (long)blockIdx.x * TILE_M + wid * 16;

    const float* xr0 = &x[(rb + g) * D_DIM];
    const float* xr1 = &x[(rb + g + 8) * D_DIM];

    float acc[4][4] = {};

#pragma unroll 4
    for (int ks = 0; ks < 16; ks++) {
        const int k0 = ks * 16 + tig * 2;
        // A fragment (16x16): a0 (r=g, k0..k0+1), a1 (r=g+8), a2 (r=g, +8), a3 (r=g+8, +8)
        float2 v0 = *reinterpret_cast<const float2*>(&xr0[k0]);
        float2 v1 = *reinterpret_cast<const float2*>(&xr1[k0]);
        float2 v2 = *reinterpret_cast<const float2*>(&xr0[k0 + 8]);
        float2 v3 = *reinterpret_cast<const float2*>(&xr1[k0 + 8]);
        uint32_t ahi[4], alo[4];
        split2(v0, ahi[0], alo[0]);
        split2(v1, ahi[1], alo[1]);
        split2(v2, ahi[2], alo[2]);
        split2(v3, ahi[3], alo[3]);

#pragma unroll
        for (int nt = 0; nt < 4; nt++) {
            uint2 bh = *reinterpret_cast<const uint2*>(&bfrag[0][ks][nt][lane * 2]);
            uint2 bl = *reinterpret_cast<const uint2*>(&bfrag[1][ks][nt][lane * 2]);
            mma16816(acc[nt], ahi, bh.x, bh.y);
            mma16816(acc[nt], alo, bh.x, bh.y);
            mma16816(acc[nt], ahi, bl.x, bl.y);
        }
    }

    // ---- epilogue: D fragment c0,c1 -> (row g, col 2tig..+1); c2,c3 -> (row g+8) ----
    const long r0 = rb + g;
    const long r1 = rb + g + 8;
#pragma unroll
    for (int nt = 0; nt < 4; nt++) {
        const int col = nt * 8 + tig * 2;
        const float b0 = bs[col], b1 = bs[col + 1];
        *reinterpret_cast<float2*>(&g_xgb[r0 * G_DIM + col]) =
            make_float2(acc[nt][0] + b0, acc[nt][1] + b1);
        *reinterpret_cast<float2*>(&g_xgb[r1 * G_DIM + col]) =
            make_float2(acc[nt][2] + b0, acc[nt][3] + b1);
    }
}

// ======================= Kernel 2: reset-segmented LSTM scan =======================
__device__ __forceinline__ float fast_sigmoid(float v) {
    v = fmaxf(v, -80.0f);
    float e = __expf(-v);
    return __fdividef(1.0f, 1.0f + e);
}
__device__ __forceinline__ float fast_tanh(float v) {
    float vc = fminf(fmaxf(v, -20.0f), 20.0f);
    float e = __expf(-2.0f * vc);
    return __fdividef(1.0f - e, 1.0f + e);
}

__global__ __launch_bounds__(256) void scan_kernel(
    const int* __restrict__ reset, const float* __restrict__ Whh,
    const float* __restrict__ Wproj, const float* __restrict__ bproj,
    float* __restrict__ out)
{
    __shared__ float wsh[G_DIM * H_DIM];
    __shared__ float wpsh[H_DIM];
    __shared__ float bpsh;
    const int tid = threadIdx.x;
    if (tid < G_DIM * H_DIM) wsh[tid] = Whh[tid];
    if (tid < H_DIM) wpsh[tid] = Wproj[tid];
    if (tid == 0) bpsh = bproj[0];
    __syncthreads();

    const int gid  = blockIdx.x * 32 + (tid >> 3);  // candidate segment start (t0,b)
    const int lane = tid & 7;
    const int t0 = gid >> 8;
    const int b  = gid & 255;

    const bool startp = (t0 == 0) || (reset[gid] != 0);
    if (!startp) return;

    const unsigned mask = 0xFFu << (((tid >> 3) & 3) << 3);

    float wi[8], wf[8], wg[8], wo[8], wp[8];
#pragma unroll
    for (int k = 0; k < 8; k++) {
        wi[k] = wsh[lane * 8 + k];
        wf[k] = wsh[(lane + 8) * 8 + k];
        wg[k] = wsh[(lane + 16) * 8 + k];
        wo[k] = wsh[(lane + 24) * 8 + k];
        wp[k] = wpsh[k];
    }
    const float bp = bpsh;

    float h[8];
#pragma unroll
    for (int k = 0; k < 8; k++) h[k] = 0.0f;
    float c = 0.0f;

    int t = t0;
    const float* xg = &g_xgb[((long)t * B_DIM + b) * G_DIM];
    float gi0 = xg[lane], gf0 = xg[lane + 8], gG0 = xg[lane + 16], go0 = xg[lane + 24];

    while (true) {
        // prefetch t+1 (h-independent) to hide load latency behind the serial chain
        const bool cont = (t + 1 < T_DIM);
        int rn = 1;
        if (cont) rn = reset[(t + 1) * B_DIM + b];
        const bool more = cont && (rn == 0);
        float ni = 0.f, nf = 0.f, nG = 0.f, no = 0.f;
        if (more) {
            const float* xg2 = &g_xgb[((long)(t + 1) * B_DIM + b) * G_DIM];
            ni = xg2[lane]; nf = xg2[lane + 8]; nG = xg2[lane + 16]; no = xg2[lane + 24];
        }

        float gi = gi0, gf = gf0, gG = gG0, go = go0;
#pragma unroll
        for (int k = 0; k < 8; k++) {
            gi = fmaf(h[k], wi[k], gi);
            gf = fmaf(h[k], wf[k], gf);
            gG = fmaf(h[k], wg[k], gG);
            go = fmaf(h[k], wo[k], go);
        }
        const float iv = fast_sigmoid(gi);
        const float fv = fast_sigmoid(gf);
        const float gv = fast_tanh(gG);
        const float ov = fast_sigmoid(go);
        c = fmaf(fv, c, iv * gv);
        const float hj = ov * fast_tanh(c);

#pragma unroll
        for (int k = 0; k < 8; k++)
            h[k] = __shfl_sync(mask, hj, k, 8);

        if (lane == 0) {
            float v = bp;
#pragma unroll
            for (int k = 0; k < 8; k++) v = fmaf(h[k], wp[k], v);
            out[t * B_DIM + b] = v;
        }

        if (!more) break;
        t++;
        gi0 = ni; gf0 = nf; gG0 = nG; go0 = no;
    }
}

// ======================= launch =======================
extern "C" void kernel_launch(void* const* d_in, const int* in_sizes, int n_in,
                              void* d_out, int out_size) {
    const float* x      = (const float*)d_in[0];
    const int*   reset  = (const int*)d_in[1];
    const float* W_ih   = (const float*)d_in[2];
    const float* W_hh   = (const float*)d_in[3];
    const float* b_ih   = (const float*)d_in[4];
    const float* b_hh   = (const float*)d_in[5];
    const float* W_proj = (const float*)d_in[6];
    const float* b_proj = (const float*)d_in[7];
    float* out = (float*)d_out;

    gemm_mma<<<M_ROWS / TILE_M, 256>>>(x, W_ih, b_ih, b_hh);
    scan_kernel<<<M_ROWS / 32, 256>>>(reset, W_hh, W_proj, b_proj, out);
}

// round 9
// speedup vs baseline: 1.4935x; 1.0447x over previous
#include <cuda_runtime.h>
#include <cuda_bf16.h>
#include <cstdint>

#define T_DIM 2048
#define B_DIM 256
#define D_DIM 256
#define G_DIM 32               // 4*H
#define H_DIM 8
#define M_ROWS (T_DIM * B_DIM) // 524288

// 64 MB scratch for gate pre-activations (x @ W_ih^T + b_ih + b_hh)
__device__ __align__(16) float g_xgb[(size_t)M_ROWS * G_DIM];
// segment worklist (compacted segment-start gids) + counter
__device__ int g_wl[M_ROWS];
__device__ int g_wl_cnt;

// ---------------- bf16 split helper: v -> (hi, lo) packed bf16x2 ----------------
__device__ __forceinline__ void split2(float2 v, uint32_t& hi, uint32_t& lo) {
    __nv_bfloat162 h = __floats2bfloat162_rn(v.x, v.y);
    float2 hf = __bfloat1622float2(h);
    __nv_bfloat162 l = __floats2bfloat162_rn(v.x - hf.x, v.y - hf.y);
    hi = *reinterpret_cast<uint32_t*>(&h);
    lo = *reinterpret_cast<uint32_t*>(&l);
}

// mma.sync m16n8k16 row.col f32.bf16.bf16.f32 (base PTX, works on compute_103)
__device__ __forceinline__ void mma16816(float c[4], const uint32_t a[4],
                                         uint32_t b0, uint32_t b1) {
    asm volatile(
        "mma.sync.aligned.m16n8k16.row.col.f32.bf16.bf16.f32 "
        "{%0,%1,%2,%3}, {%4,%5,%6,%7}, {%8,%9}, {%0,%1,%2,%3};"
        : "+f"(c[0]), "+f"(c[1]), "+f"(c[2]), "+f"(c[3])
        : "r"(a[0]), "r"(a[1]), "r"(a[2]), "r"(a[3]), "r"(b0), "r"(b1));
}

// ======================= Kernel 1: gates GEMM on HMMA (unchanged) =======================
#define TILE_M 128

__global__ __launch_bounds__(256) void gemm_mma(
    const float* __restrict__ x, const float* __restrict__ W,
    const float* __restrict__ bih, const float* __restrict__ bhh)
{
    __shared__ __align__(16) uint32_t bfrag[2][16][4][64];
    __shared__ float bs[G_DIM];

    const int tid = threadIdx.x;
    if (tid < G_DIM) bs[tid] = bih[tid] + bhh[tid];

    for (int e = tid; e < 4096; e += 256) {
        const int reg = e & 1;
        const int lane = (e >> 1) & 31;
        const int nt  = (e >> 6) & 3;
        const int ks  = e >> 8;
        const int g   = lane >> 2, tig = lane & 3;
        const int n   = nt * 8 + g;
        const int k   = ks * 16 + tig * 2 + reg * 8;
        float2 w = *reinterpret_cast<const float2*>(&W[n * D_DIM + k]);
        uint32_t hp, lp;
        split2(w, hp, lp);
        bfrag[0][ks][nt][lane * 2 + reg] = hp;
        bfrag[1][ks][nt][lane * 2 + reg] = lp;
    }
    __syncthreads();

    const int wid  = tid >> 5;
    const int lane = tid & 31;
    const int g    = lane >> 2;
    const int tig  = lane & 3;
    const long rb  = (long)blockIdx.x * TILE_M + wid * 16;

    const float* xr0 = &x[(rb + g) * D_DIM];
    const float* xr1 = &x[(rb + g + 8) * D_DIM];

    float acc[4][4] = {};

#pragma unroll 4
    for (int ks = 0; ks < 16; ks++) {
        const int k0 = ks * 16 + tig * 2;
        float2 v0 = *reinterpret_cast<const float2*>(&xr0[k0]);
        float2 v1 = *reinterpret_cast<const float2*>(&xr1[k0]);
        float2 v2 = *reinterpret_cast<const float2*>(&xr0[k0 + 8]);
        float2 v3 = *reinterpret_cast<const float2*>(&xr1[k0 + 8]);
        uint32_t ahi[4], alo[4];
        split2(v0, ahi[0], alo[0]);
        split2(v1, ahi[1], alo[1]);
        split2(v2, ahi[2], alo[2]);
        split2(v3, ahi[3], alo[3]);

#pragma unroll
        for (int nt = 0; nt < 4; nt++) {
            uint2 bh = *reinterpret_cast<const uint2*>(&bfrag[0][ks][nt][lane * 2]);
            uint2 bl = *reinterpret_cast<const uint2*>(&bfrag[1][ks][nt][lane * 2]);
            mma16816(acc[nt], ahi, bh.x, bh.y);
            mma16816(acc[nt], alo, bh.x, bh.y);
            mma16816(acc[nt], ahi, bl.x, bl.y);
        }
    }

    const long r0 = rb + g;
    const long r1 = rb + g + 8;
#pragma unroll
    for (int nt = 0; nt < 4; nt++) {
        const int col = nt * 8 + tig * 2;
        const float b0 = bs[col], b1 = bs[col + 1];
        *reinterpret_cast<float2*>(&g_xgb[r0 * G_DIM + col]) =
            make_float2(acc[nt][0] + b0, acc[nt][1] + b1);
        *reinterpret_cast<float2*>(&g_xgb[r1 * G_DIM + col]) =
            make_float2(acc[nt][2] + b0, acc[nt][3] + b1);
    }
}

// ======================= worklist build =======================
__global__ void zero_cnt_kernel() { g_wl_cnt = 0; }

__global__ __launch_bounds__(256) void compact_kernel(const int* __restrict__ reset) {
    const int gid = blockIdx.x * 256 + threadIdx.x;          // gid = t0*256 + b
    const bool start = (gid < M_ROWS) && ((gid >> 8) == 0 || reset[gid] != 0);
    const unsigned bal = __ballot_sync(0xFFFFFFFFu, start);
    if (!bal) return;
    int base = 0;
    if ((threadIdx.x & 31) == 0) base = atomicAdd(&g_wl_cnt, __popc(bal));
    base = __shfl_sync(0xFFFFFFFFu, base, 0);
    if (start) {
        const int rank = __popc(bal & ((1u << (threadIdx.x & 31)) - 1u));
        g_wl[base + rank] = gid;
    }
}

// ======================= Kernel 2: streaming segmented LSTM scan =======================
__device__ __forceinline__ float tanh_mufu(float x) {
    float y;
    asm("tanh.approx.f32 %0, %1;" : "=f"(y) : "f"(x));
    return y;
}
__device__ __forceinline__ float sig_mufu(float x) {
    return fmaf(0.5f, tanh_mufu(0.5f * x), 0.5f);
}

#define SCAN_BLOCKS 1024
#define TOT_SLOTS (SCAN_BLOCKS * 32)

__global__ __launch_bounds__(256) void scan_kernel(
    const int* __restrict__ reset, const float* __restrict__ Whh,
    const float* __restrict__ Wproj, const float* __restrict__ bproj,
    float* __restrict__ out)
{
    __shared__ float wsh[G_DIM * H_DIM];
    __shared__ float wpsh[H_DIM];
    __shared__ float bpsh;
    const int tid = threadIdx.x;
    if (tid < G_DIM * H_DIM) wsh[tid] = Whh[tid];
    if (tid < H_DIM) wpsh[tid] = Wproj[tid];
    if (tid == 0) bpsh = bproj[0];
    __syncthreads();

    const int lane = tid & 7;
    const unsigned gmask = 0xFFu << (((tid >> 3) & 3) << 3);   // this 8-lane group
    const int count = g_wl_cnt;

    // Lane j holds W_hh rows {j, j+8, j+16, j+24} (i, f, g, o)
    float wi[8], wf[8], wg[8], wo[8], wp[8];
#pragma unroll
    for (int k = 0; k < 8; k++) {
        wi[k] = wsh[lane * 8 + k];
        wf[k] = wsh[(lane + 8) * 8 + k];
        wg[k] = wsh[(lane + 16) * 8 + k];
        wo[k] = wsh[(lane + 24) * 8 + k];
        wp[k] = wpsh[k];
    }
    const float bp = bpsh;

    int idx = blockIdx.x * 32 + (tid >> 3);   // this group's worklist cursor
    bool active = false;
    int t = 0, b = 0;
    float h[8], c = 0.0f;
    float gi0 = 0.f, gf0 = 0.f, gG0 = 0.f, go0 = 0.f;

    while (true) {
        // fetch a new segment when idle (group-uniform branch)
        if (!active && idx < count) {
            const int gid = g_wl[idx];
            idx += TOT_SLOTS;
            t = gid >> 8;
            b = gid & 255;
#pragma unroll
            for (int k = 0; k < 8; k++) h[k] = 0.0f;
            c = 0.0f;
            const float* xg = &g_xgb[((long)t * B_DIM + b) * G_DIM];
            gi0 = xg[lane]; gf0 = xg[lane + 8]; gG0 = xg[lane + 16]; go0 = xg[lane + 24];
            active = true;
        }
        if (__all_sync(0xFFFFFFFFu, !active)) break;

        if (active) {
            // prefetch t+1 (h-independent)
            const bool cont = (t + 1 < T_DIM);
            int rn = 1;
            if (cont) rn = reset[(t + 1) * B_DIM + b];
            const bool more = cont && (rn == 0);
            float ni = 0.f, nf = 0.f, nG = 0.f, no = 0.f;
            if (more) {
                const float* xg2 = &g_xgb[((long)(t + 1) * B_DIM + b) * G_DIM];
                ni = xg2[lane]; nf = xg2[lane + 8]; nG = xg2[lane + 16]; no = xg2[lane + 24];
            }

            float gi = gi0, gf = gf0, gG = gG0, go = go0;
#pragma unroll
            for (int k = 0; k < 8; k++) {
                gi = fmaf(h[k], wi[k], gi);
                gf = fmaf(h[k], wf[k], gf);
                gG = fmaf(h[k], wg[k], gG);
                go = fmaf(h[k], wo[k], go);
            }
            const float iv = sig_mufu(gi);
            const float fv = sig_mufu(gf);
            const float gv = tanh_mufu(gG);
            const float ov = sig_mufu(go);
            c = fmaf(fv, c, iv * gv);
            const float hj = ov * tanh_mufu(c);

#pragma unroll
            for (int k = 0; k < 8; k++)
                h[k] = __shfl_sync(gmask, hj, k, 8);

            if (lane == 0) {
                float v = bp;
#pragma unroll
                for (int k = 0; k < 8; k++) v = fmaf(h[k], wp[k], v);
                out[t * B_DIM + b] = v;
            }

            if (more) {
                t++;
                gi0 = ni; gf0 = nf; gG0 = nG; go0 = no;
            } else {
                active = false;
            }
        }
    }
}

// ======================= launch =======================
extern "C" void kernel_launch(void* const* d_in, const int* in_sizes, int n_in,
                              void* d_out, int out_size) {
    const float* x      = (const float*)d_in[0];
    const int*   reset  = (const int*)d_in[1];
    const float* W_ih   = (const float*)d_in[2];
    const float* W_hh   = (const float*)d_in[3];
    const float* b_ih   = (const float*)d_in[4];
    const float* b_hh   = (const float*)d_in[5];
    const float* W_proj = (const float*)d_in[6];
    const float* b_proj = (const float*)d_in[7];
    float* out = (float*)d_out;

    zero_cnt_kernel<<<1, 1>>>();
    compact_kernel<<<M_ROWS / 256, 256>>>(reset);
    gemm_mma<<<M_ROWS / TILE_M, 256>>>(x, W_ih, b_ih, b_hh);
    scan_kernel<<<SCAN_BLOCKS, 256>>>(reset, W_hh, W_proj, b_proj, out);
}

// round 12
// speedup vs baseline: 1.8082x; 1.2107x over previous
#include <cuda_runtime.h>
#include <cuda_bf16.h>
#include <cstdint>

#define T_DIM 2048
#define B_DIM 256
#define D_DIM 256
#define G_DIM 32               // 4*H
#define H_DIM 8
#define M_ROWS (T_DIM * B_DIM) // 524288

// 64 MB scratch for gate pre-activations (x @ W_ih^T + b_ih + b_hh)
__device__ __align__(16) float g_xgb[(size_t)M_ROWS * G_DIM];
// segment worklist (compacted segment-start gids) + counter
__device__ int g_wl[M_ROWS];
__device__ int g_wl_cnt;

// ---------------- bf16 split helper: v -> (hi, lo) packed bf16x2 ----------------
__device__ __forceinline__ void split2(float2 v, uint32_t& hi, uint32_t& lo) {
    __nv_bfloat162 h = __floats2bfloat162_rn(v.x, v.y);
    float2 hf = __bfloat1622float2(h);
    __nv_bfloat162 l = __floats2bfloat162_rn(v.x - hf.x, v.y - hf.y);
    hi = *reinterpret_cast<uint32_t*>(&h);
    lo = *reinterpret_cast<uint32_t*>(&l);
}

// mma.sync m16n8k16 row.col f32.bf16.bf16.f32 (base PTX, works on compute_103)
__device__ __forceinline__ void mma16816(float c[4], const uint32_t a[4],
                                         uint32_t b0, uint32_t b1) {
    asm volatile(
        "mma.sync.aligned.m16n8k16.row.col.f32.bf16.bf16.f32 "
        "{%0,%1,%2,%3}, {%4,%5,%6,%7}, {%8,%9}, {%0,%1,%2,%3};"
        : "+f"(c[0]), "+f"(c[1]), "+f"(c[2]), "+f"(c[3])
        : "r"(a[0]), "r"(a[1]), "r"(a[2]), "r"(a[3]), "r"(b0), "r"(b1));
}

// ======================= Kernel 1: gates GEMM on HMMA (unchanged) =======================
#define TILE_M 128

__global__ __launch_bounds__(256) void gemm_mma(
    const float* __restrict__ x, const float* __restrict__ W,
    const float* __restrict__ bih, const float* __restrict__ bhh)
{
    __shared__ __align__(16) uint32_t bfrag[2][16][4][64];
    __shared__ float bs[G_DIM];

    const int tid = threadIdx.x;
    if (tid < G_DIM) bs[tid] = bih[tid] + bhh[tid];

    for (int e = tid; e < 4096; e += 256) {
        const int reg = e & 1;
        const int lane = (e >> 1) & 31;
        const int nt  = (e >> 6) & 3;
        const int ks  = e >> 8;
        const int g   = lane >> 2, tig = lane & 3;
        const int n   = nt * 8 + g;
        const int k   = ks * 16 + tig * 2 + reg * 8;
        float2 w = *reinterpret_cast<const float2*>(&W[n * D_DIM + k]);
        uint32_t hp, lp;
        split2(w, hp, lp);
        bfrag[0][ks][nt][lane * 2 + reg] = hp;
        bfrag[1][ks][nt][lane * 2 + reg] = lp;
    }
    __syncthreads();

    const int wid  = tid >> 5;
    const int lane = tid & 31;
    const int g    = lane >> 2;
    const int tig  = lane & 3;
    const long rb  = (long)blockIdx.x * TILE_M + wid * 16;

    const float* xr0 = &x[(rb + g) * D_DIM];
    const float* xr1 = &x[(rb + g + 8) * D_DIM];

    float acc[4][4] = {};

#pragma unroll 4
    for (int ks = 0; ks < 16; ks++) {
        const int k0 = ks * 16 + tig * 2;
        float2 v0 = *reinterpret_cast<const float2*>(&xr0[k0]);
        float2 v1 = *reinterpret_cast<const float2*>(&xr1[k0]);
        float2 v2 = *reinterpret_cast<const float2*>(&xr0[k0 + 8]);
        float2 v3 = *reinterpret_cast<const float2*>(&xr1[k0 + 8]);
        uint32_t ahi[4], alo[4];
        split2(v0, ahi[0], alo[0]);
        split2(v1, ahi[1], alo[1]);
        split2(v2, ahi[2], alo[2]);
        split2(v3, ahi[3], alo[3]);

#pragma unroll
        for (int nt = 0; nt < 4; nt++) {
            uint2 bh = *reinterpret_cast<const uint2*>(&bfrag[0][ks][nt][lane * 2]);
            uint2 bl = *reinterpret_cast<const uint2*>(&bfrag[1][ks][nt][lane * 2]);
            mma16816(acc[nt], ahi, bh.x, bh.y);
            mma16816(acc[nt], alo, bh.x, bh.y);
            mma16816(acc[nt], ahi, bl.x, bl.y);
        }
    }

    const long r0 = rb + g;
    const long r1 = rb + g + 8;
#pragma unroll
    for (int nt = 0; nt < 4; nt++) {
        const int col = nt * 8 + tig * 2;
        const float b0 = bs[col], b1 = bs[col + 1];
        *reinterpret_cast<float2*>(&g_xgb[r0 * G_DIM + col]) =
            make_float2(acc[nt][0] + b0, acc[nt][1] + b1);
        *reinterpret_cast<float2*>(&g_xgb[r1 * G_DIM + col]) =
            make_float2(acc[nt][2] + b0, acc[nt][3] + b1);
    }
}

// ======================= worklist build =======================
__global__ void zero_cnt_kernel() { g_wl_cnt = 0; }

__global__ __launch_bounds__(256) void compact_kernel(const int* __restrict__ reset) {
    const int gid = blockIdx.x * 256 + threadIdx.x;          // gid = t0*256 + b
    const bool start = (gid < M_ROWS) && ((gid >> 8) == 0 || reset[gid] != 0);
    const unsigned bal = __ballot_sync(0xFFFFFFFFu, start);
    if (!bal) return;
    int base = 0;
    if ((threadIdx.x & 31) == 0) base = atomicAdd(&g_wl_cnt, __popc(bal));
    base = __shfl_sync(0xFFFFFFFFu, base, 0);
    if (start) {
        const int rank = __popc(bal & ((1u << (threadIdx.x & 31)) - 1u));
        g_wl[base + rank] = gid;
    }
}

// ======================= Kernel 2: one-thread-per-segment LSTM scan =======================
__device__ __forceinline__ float tanh_mufu(float x) {
    float y;
    asm("tanh.approx.f32 %0, %1;" : "=f"(y) : "f"(x));
    return y;
}
__device__ __forceinline__ float sig_mufu(float x) {
    return fmaf(0.5f, tanh_mufu(0.5f * x), 0.5f);
}

#define SCAN_TPB 128
#define LANES 32768
#define SCAN_BLOCKS (LANES / SCAN_TPB)   // 256

// acc += dot(h[0..7], wsh[base..base+7])  -- uniform LDS.128 broadcast
#define DOT8(acc, base) do {                                                   \
    float4 _wa = *reinterpret_cast<const float4*>(&wsh[(base)]);               \
    float4 _wb = *reinterpret_cast<const float4*>(&wsh[(base) + 4]);           \
    acc = fmaf(h[0], _wa.x, acc); acc = fmaf(h[1], _wa.y, acc);                \
    acc = fmaf(h[2], _wa.z, acc); acc = fmaf(h[3], _wa.w, acc);                \
    acc = fmaf(h[4], _wb.x, acc); acc = fmaf(h[5], _wb.y, acc);                \
    acc = fmaf(h[6], _wb.z, acc); acc = fmaf(h[7], _wb.w, acc);                \
} while (0)

__global__ __launch_bounds__(SCAN_TPB) void scan_kernel(
    const int* __restrict__ reset, const float* __restrict__ Whh,
    const float* __restrict__ Wproj, const float* __restrict__ bproj,
    float* __restrict__ out)
{
    __shared__ __align__(16) float wsh[G_DIM * H_DIM];   // [gate row][k]
    __shared__ float wpsh[H_DIM];
    __shared__ float bpsh;
    const int tid = threadIdx.x;
    wsh[tid] = Whh[tid];
    wsh[tid + 128] = Whh[tid + 128];
    if (tid < H_DIM) wpsh[tid] = Wproj[tid];
    if (tid == 0) bpsh = bproj[0];
    __syncthreads();

    float wp[8];
#pragma unroll
    for (int k = 0; k < 8; k++) wp[k] = wpsh[k];
    const float bp = bpsh;

    const int count = g_wl_cnt;
    int idx = blockIdx.x * SCAN_TPB + tid;

    int next_gid = -1;
    if (idx < count) { next_gid = g_wl[idx]; idx += LANES; }

    float h[8], cs[8], cg[32];
#pragma unroll
    for (int k = 0; k < 8; k++) { h[k] = 0.0f; cs[k] = 0.0f; }

    int t = 0, b = 0;
    bool active = (next_gid >= 0);
    if (active) {
        t = next_gid >> 8;
        b = next_gid & 255;
        const float4* rp = reinterpret_cast<const float4*>(&g_xgb[((long)t * B_DIM + b) * G_DIM]);
#pragma unroll
        for (int q = 0; q < 8; q++) *reinterpret_cast<float4*>(&cg[q * 4]) = rp[q];
        next_gid = -1;
        if (idx < count) { next_gid = g_wl[idx]; idx += LANES; }
    }

    while (active) {   // per-lane independent loop: no warp collectives inside
        // --- decide next row & prefetch it (continuation or next segment start) ---
        int rn = 1;
        if (t + 1 < T_DIM) rn = reset[(t + 1) * B_DIM + b];
        const bool more = (rn == 0);
        bool consume = false, nactive;
        int nt, nb;
        if (more)               { nt = t + 1;           nb = b;              nactive = true; }
        else if (next_gid >= 0) { nt = next_gid >> 8;   nb = next_gid & 255; nactive = true; consume = true; }
        else                    { nt = t;               nb = b;              nactive = false; }

        float ng[32];
        {
            const float4* rp = reinterpret_cast<const float4*>(&g_xgb[((long)nt * B_DIM + nb) * G_DIM]);
#pragma unroll
            for (int q = 0; q < 8; q++) *reinterpret_cast<float4*>(&ng[q * 4]) = rp[q];
        }

        // --- LSTM cell: all 8 hidden units in this thread ---
        float hn[8];
#pragma unroll
        for (int j = 0; j < 8; j++) {
            float gi = cg[j], gf = cg[8 + j], gg = cg[16 + j], go = cg[24 + j];
            DOT8(gi, j * 8);
            DOT8(gf, (8 + j) * 8);
            DOT8(gg, (16 + j) * 8);
            DOT8(go, (24 + j) * 8);
            const float iv = sig_mufu(gi);
            const float fv = sig_mufu(gf);
            const float gv = tanh_mufu(gg);
            const float ov = sig_mufu(go);
            cs[j] = fmaf(fv, cs[j], iv * gv);
            hn[j] = ov * tanh_mufu(cs[j]);
        }
#pragma unroll
        for (int j = 0; j < 8; j++) h[j] = hn[j];

        float v = bp;
#pragma unroll
        for (int k = 0; k < 8; k++) v = fmaf(h[k], wp[k], v);
        out[t * B_DIM + b] = v;

        // --- advance ---
        if (!more) {
#pragma unroll
            for (int j = 0; j < 8; j++) { h[j] = 0.0f; cs[j] = 0.0f; }
            if (consume) {
                next_gid = -1;
                if (idx < count) { next_gid = g_wl[idx]; idx += LANES; }
            }
        }
        t = nt; b = nb;
        active = nactive;
#pragma unroll
        for (int q = 0; q < 32; q++) cg[q] = ng[q];
    }
}

// ======================= launch =======================
extern "C" void kernel_launch(void* const* d_in, const int* in_sizes, int n_in,
                              void* d_out, int out_size) {
    const float* x      = (const float*)d_in[0];
    const int*   reset  = (const int*)d_in[1];
    const float* W_ih   = (const float*)d_in[2];
    const float* W_hh   = (const float*)d_in[3];
    const float* b_ih   = (const float*)d_in[4];
    const float* b_hh   = (const float*)d_in[5];
    const float* W_proj = (const float*)d_in[6];
    const float* b_proj = (const float*)d_in[7];
    float* out = (float*)d_out;

    zero_cnt_kernel<<<1, 1>>>();
    compact_kernel<<<M_ROWS / 256, 256>>>(reset);
    gemm_mma<<<M_ROWS / TILE_M, 256>>>(x, W_ih, b_ih, b_hh);
    scan_kernel<<<SCAN_BLOCKS, SCAN_TPB>>>(reset, W_hh, W_proj, b_proj, out);
}

// round 14
// speedup vs baseline: 1.8766x; 1.0378x over previous
#include <cuda_runtime.h>
#include <cuda_bf16.h>
#include <cstdint>

#define T_DIM 2048
#define B_DIM 256
#define D_DIM 256
#define G_DIM 32               // 4*H
#define H_DIM 8
#define M_ROWS (T_DIM * B_DIM) // 524288

// 64 MB scratch for gate pre-activations (x @ W_ih^T + b_ih + b_hh)
__device__ __align__(16) float g_xgb[(size_t)M_ROWS * G_DIM];
// segment worklist (compacted segment-start gids) + counter
__device__ int g_wl[M_ROWS];
__device__ int g_wl_cnt;

// ---------------- bf16 split helper: v -> (hi, lo) packed bf16x2 ----------------
__device__ __forceinline__ void split2(float2 v, uint32_t& hi, uint32_t& lo) {
    __nv_bfloat162 h = __floats2bfloat162_rn(v.x, v.y);
    float2 hf = __bfloat1622float2(h);
    __nv_bfloat162 l = __floats2bfloat162_rn(v.x - hf.x, v.y - hf.y);
    hi = *reinterpret_cast<uint32_t*>(&h);
    lo = *reinterpret_cast<uint32_t*>(&l);
}

// mma.sync m16n8k16 row.col f32.bf16.bf16.f32 (base PTX, works on compute_103)
__device__ __forceinline__ void mma16816(float c[4], const uint32_t a[4],
                                         uint32_t b0, uint32_t b1) {
    asm volatile(
        "mma.sync.aligned.m16n8k16.row.col.f32.bf16.bf16.f32 "
        "{%0,%1,%2,%3}, {%4,%5,%6,%7}, {%8,%9}, {%0,%1,%2,%3};"
        : "+f"(c[0]), "+f"(c[1]), "+f"(c[2]), "+f"(c[3])
        : "r"(a[0]), "r"(a[1]), "r"(a[2]), "r"(a[3]), "r"(b0), "r"(b1));
}

// ======================= Kernel 1: gates GEMM on HMMA =======================
// g_xgb[r][g] = sum_k x[r][k]*W[g][k] + b_ih[g] + b_hh[g]
// 3-term bf16 split: D += Ahi*Bhi + Alo*Bhi + Ahi*Blo
// k-PERMUTED fragments: MMA-k {2tig,2tig+1,2tig+8,2tig+9} <- cols {4tig..4tig+3}
// so each A-fragment row is ONE float4 load. B prepacked with the same permutation.
// CTA: 256 rows; 8 warps x 32 rows (2 m-tiles of 16); N=32 (4 n-tiles); 16 k-steps.
#define TILE_M 256

__global__ __launch_bounds__(256) void gemm_mma(
    const float* __restrict__ x, const float* __restrict__ W,
    const float* __restrict__ bih, const float* __restrict__ bhh)
{
    // B fragments prepacked: [term(hi/lo)][ks][nt][lane*2 + reg]  (uint2 per lane)
    __shared__ __align__(16) uint32_t bfrag[2][16][4][64];
    __shared__ float bs[G_DIM];

    const int tid = threadIdx.x;
    if (tid < G_DIM) bs[tid] = bih[tid] + bhh[tid];

    // ---- prepack W (fp32 -> bf16 hi/lo) into PERMUTED B-fragment layout ----
    // b-reg0 (MMA-k 2tig,2tig+1)   <- W[n][ks*16 + tig*4 + 0..1]
    // b-reg1 (MMA-k 2tig+8,2tig+9) <- W[n][ks*16 + tig*4 + 2..3]
    for (int e = tid; e < 4096; e += 256) {
        const int reg  = e & 1;
        const int lane = (e >> 1) & 31;
        const int nt   = (e >> 6) & 3;
        const int ks   = e >> 8;
        const int n    = nt * 8 + (lane >> 2);
        const int k    = ks * 16 + (lane & 3) * 4 + reg * 2;
        float2 w = *reinterpret_cast<const float2*>(&W[n * D_DIM + k]);
        uint32_t hp, lp;
        split2(w, hp, lp);
        bfrag[0][ks][nt][lane * 2 + reg] = hp;
        bfrag[1][ks][nt][lane * 2 + reg] = lp;
    }
    __syncthreads();

    const int wid  = tid >> 5;
    const int lane = tid & 31;
    const int g    = lane >> 2;
    const int tig  = lane & 3;
    const long rb  = (long)blockIdx.x * TILE_M + wid * 32;

    const float* xr00 = &x[(rb + g) * D_DIM];        // m-tile 0, row g
    const float* xr01 = &x[(rb + g + 8) * D_DIM];    // m-tile 0, row g+8
    const float* xr10 = &x[(rb + 16 + g) * D_DIM];   // m-tile 1, row g
    const float* xr11 = &x[(rb + 24 + g) * D_DIM];   // m-tile 1, row g+8

    float acc[2][4][4] = {};

#pragma unroll 4
    for (int ks = 0; ks < 16; ks++) {
        const int k0 = ks * 16 + tig * 4;
        const float4 v00 = *reinterpret_cast<const float4*>(&xr00[k0]);
        const float4 v01 = *reinterpret_cast<const float4*>(&xr01[k0]);
        const float4 v10 = *reinterpret_cast<const float4*>(&xr10[k0]);
        const float4 v11 = *reinterpret_cast<const float4*>(&xr11[k0]);

        // A fragments under the k-permutation:
        //   a0 <- v.xy (MMA-k 2tig,2tig+1, row g),  a1 <- row g+8
        //   a2 <- v.zw (MMA-k 2tig+8,2tig+9),       a3 <- row g+8
        uint32_t ahi0[4], alo0[4], ahi1[4], alo1[4];
        split2(make_float2(v00.x, v00.y), ahi0[0], alo0[0]);
        split2(make_float2(v01.x, v01.y), ahi0[1], alo0[1]);
        split2(make_float2(v00.z, v00.w), ahi0[2], alo0[2]);
        split2(make_float2(v01.z, v01.w), ahi0[3], alo0[3]);
        split2(make_float2(v10.x, v10.y), ahi1[0], alo1[0]);
        split2(make_float2(v11.x, v11.y), ahi1[1], alo1[1]);
        split2(make_float2(v10.z, v10.w), ahi1[2], alo1[2]);
        split2(make_float2(v11.z, v11.w), ahi1[3], alo1[3]);

#pragma unroll
        for (int nt = 0; nt < 4; nt++) {
            const uint2 bh = *reinterpret_cast<const uint2*>(&bfrag[0][ks][nt][lane * 2]);
            const uint2 bl = *reinterpret_cast<const uint2*>(&bfrag[1][ks][nt][lane * 2]);
            mma16816(acc[0][nt], ahi0, bh.x, bh.y);
            mma16816(acc[0][nt], alo0, bh.x, bh.y);
            mma16816(acc[0][nt], ahi0, bl.x, bl.y);
            mma16816(acc[1][nt], ahi1, bh.x, bh.y);
            mma16816(acc[1][nt], alo1, bh.x, bh.y);
            mma16816(acc[1][nt], ahi1, bl.x, bl.y);
        }
    }

    // ---- epilogue: c0,c1 -> (row g, col 2tig..+1); c2,c3 -> (row g+8) ----
#pragma unroll
    for (int mt = 0; mt < 2; mt++) {
        const long r0 = rb + mt * 16 + g;
        const long r1 = r0 + 8;
#pragma unroll
        for (int nt = 0; nt < 4; nt++) {
            const int col = nt * 8 + tig * 2;
            const float b0 = bs[col], b1 = bs[col + 1];
            *reinterpret_cast<float2*>(&g_xgb[r0 * G_DIM + col]) =
                make_float2(acc[mt][nt][0] + b0, acc[mt][nt][1] + b1);
            *reinterpret_cast<float2*>(&g_xgb[r1 * G_DIM + col]) =
                make_float2(acc[mt][nt][2] + b0, acc[mt][nt][3] + b1);
        }
    }
}

// ======================= worklist build =======================
__global__ void zero_cnt_kernel() { g_wl_cnt = 0; }

__global__ __launch_bounds__(256) void compact_kernel(const int* __restrict__ reset) {
    const int gid = blockIdx.x * 256 + threadIdx.x;          // gid = t0*256 + b
    const bool start = (gid < M_ROWS) && ((gid >> 8) == 0 || reset[gid] != 0);
    const unsigned bal = __ballot_sync(0xFFFFFFFFu, start);
    if (!bal) return;
    int base = 0;
    if ((threadIdx.x & 31) == 0) base = atomicAdd(&g_wl_cnt, __popc(bal));
    base = __shfl_sync(0xFFFFFFFFu, base, 0);
    if (start) {
        const int rank = __popc(bal & ((1u << (threadIdx.x & 31)) - 1u));
        g_wl[base + rank] = gid;
    }
}

// ======================= Kernel 2: one-thread-per-segment LSTM scan =======================
__device__ __forceinline__ float tanh_mufu(float x) {
    float y;
    asm("tanh.approx.f32 %0, %1;" : "=f"(y) : "f"(x));
    return y;
}
__device__ __forceinline__ float sig_mufu(float x) {
    return fmaf(0.5f, tanh_mufu(0.5f * x), 0.5f);
}

#define SCAN_TPB 128
#define LANES 32768
#define SCAN_BLOCKS (LANES / SCAN_TPB)   // 256

// acc += dot(h[0..7], wsh[base..base+7])  -- uniform LDS.128 broadcast
#define DOT8(acc, base) do {                                                   \
    float4 _wa = *reinterpret_cast<const float4*>(&wsh[(base)]);               \
    float4 _wb = *reinterpret_cast<const float4*>(&wsh[(base) + 4]);           \
    acc = fmaf(h[0], _wa.x, acc); acc = fmaf(h[1], _wa.y, acc);                \
    acc = fmaf(h[2], _wa.z, acc); acc = fmaf(h[3], _wa.w, acc);                \
    acc = fmaf(h[4], _wb.x, acc); acc = fmaf(h[5], _wb.y, acc);                \
    acc = fmaf(h[6], _wb.z, acc); acc = fmaf(h[7], _wb.w, acc);                \
} while (0)

__global__ __launch_bounds__(SCAN_TPB) void scan_kernel(
    const int* __restrict__ reset, const float* __restrict__ Whh,
    const float* __restrict__ Wproj, const float* __restrict__ bproj,
    float* __restrict__ out)
{
    __shared__ __align__(16) float wsh[G_DIM * H_DIM];   // [gate row][k]
    __shared__ float wpsh[H_DIM];
    __shared__ float bpsh;
    const int tid = threadIdx.x;
    wsh[tid] = Whh[tid];
    wsh[tid + 128] = Whh[tid + 128];
    if (tid < H_DIM) wpsh[tid] = Wproj[tid];
    if (tid == 0) bpsh = bproj[0];
    __syncthreads();

    float wp[8];
#pragma unroll
    for (int k = 0; k < 8; k++) wp[k] = wpsh[k];
    const float bp = bpsh;

    const int count = g_wl_cnt;
    int idx = blockIdx.x * SCAN_TPB + tid;

    int next_gid = -1;
    if (idx < count) { next_gid = g_wl[idx]; idx += LANES; }

    float h[8], cs[8], cg[32];
#pragma unroll
    for (int k = 0; k < 8; k++) { h[k] = 0.0f; cs[k] = 0.0f; }

    int t = 0, b = 0;
    bool active = (next_gid >= 0);
    if (active) {
        t = next_gid >> 8;
        b = next_gid & 255;
        const float4* rp = reinterpret_cast<const float4*>(&g_xgb[((long)t * B_DIM + b) * G_DIM]);
#pragma unroll
        for (int q = 0; q < 8; q++) *reinterpret_cast<float4*>(&cg[q * 4]) = rp[q];
        next_gid = -1;
        if (idx < count) { next_gid = g_wl[idx]; idx += LANES; }
    }

    while (active) {   // per-lane independent loop: no warp collectives inside
        // --- decide next row & prefetch it (continuation or next segment start) ---
        int rn = 1;
        if (t + 1 < T_DIM) rn = reset[(t + 1) * B_DIM + b];
        const bool more = (rn == 0);
        bool consume = false, nactive;
        int nt, nb;
        if (more)               { nt = t + 1;           nb = b;              nactive = true; }
        else if (next_gid >= 0) { nt = next_gid >> 8;   nb = next_gid & 255; nactive = true; consume = true; }
        else                    { nt = t;               nb = b;              nactive = false; }

        float ng[32];
        {
            const float4* rp = reinterpret_cast<const float4*>(&g_xgb[((long)nt * B_DIM + nb) * G_DIM]);
#pragma unroll
            for (int q = 0; q < 8; q++) *reinterpret_cast<float4*>(&ng[q * 4]) = rp[q];
        }

        // --- LSTM cell: all 8 hidden units in this thread ---
        float hn[8];
#pragma unroll
        for (int j = 0; j < 8; j++) {
            float gi = cg[j], gf = cg[8 + j], gg = cg[16 + j], go = cg[24 + j];
            DOT8(gi, j * 8);
            DOT8(gf, (8 + j) * 8);
            DOT8(gg, (16 + j) * 8);
            DOT8(go, (24 + j) * 8);
            const float iv = sig_mufu(gi);
            const float fv = sig_mufu(gf);
            const float gv = tanh_mufu(gg);
            const float ov = sig_mufu(go);
            cs[j] = fmaf(fv, cs[j], iv * gv);
            hn[j] = ov * tanh_mufu(cs[j]);
        }
#pragma unroll
        for (int j = 0; j < 8; j++) h[j] = hn[j];

        float v = bp;
#pragma unroll
        for (int k = 0; k < 8; k++) v = fmaf(h[k], wp[k], v);
        out[t * B_DIM + b] = v;

        // --- advance ---
        if (!more) {
#pragma unroll
            for (int j = 0; j < 8; j++) { h[j] = 0.0f; cs[j] = 0.0f; }
            if (consume) {
                next_gid = -1;
                if (idx < count) { next_gid = g_wl[idx]; idx += LANES; }
            }
        }
        t = nt; b = nb;
        active = nactive;
#pragma unroll
        for (int q = 0; q < 32; q++) cg[q] = ng[q];
    }
}

// ======================= launch =======================
extern "C" void kernel_launch(void* const* d_in, const int* in_sizes, int n_in,
                              void* d_out, int out_size) {
    const float* x      = (const float*)d_in[0];
    const int*   reset  = (const int*)d_in[1];
    const float* W_ih   = (const float*)d_in[2];
    const float* W_hh   = (const float*)d_in[3];
    const float* b_ih   = (const float*)d_in[4];
    const float* b_hh   = (const float*)d_in[5];
    const float* W_proj = (const float*)d_in[6];
    const float* b_proj = (const float*)d_in[7];
    float* out = (float*)d_out;

    zero_cnt_kernel<<<1, 1>>>();
    compact_kernel<<<M_ROWS / 256, 256>>>(reset);
    gemm_mma<<<M_ROWS / TILE_M, 256>>>(x, W_ih, b_ih, b_hh);
    scan_kernel<<<SCAN_BLOCKS, SCAN_TPB>>>(reset, W_hh, W_proj, b_proj, out);
}

// round 15
// speedup vs baseline: 1.9949x; 1.0630x over previous
#include <cuda_runtime.h>
#include <cuda_fp16.h>
#include <cstdint>

#define T_DIM 2048
#define B_DIM 256
#define D_DIM 256
#define G_DIM 32               // 4*H
#define H_DIM 8
#define M_ROWS (T_DIM * B_DIM) // 524288

// 64 MB scratch for gate pre-activations (x @ W_ih^T + b_ih + b_hh)
__device__ __align__(16) float g_xgb[(size_t)M_ROWS * G_DIM];
// segment worklist: entry = gid | (len << 19)   (gid < 2^19, len <= 2048)
__device__ int g_wl[M_ROWS];
__device__ int g_wl_cnt;

// ---------------- fp16 split helper: v -> (hi, lo) packed fp16x2 ----------------
__device__ __forceinline__ void split2h(float2 v, uint32_t& hi, uint32_t& lo) {
    __half2 h = __floats2half2_rn(v.x, v.y);
    float2 hf = __half22float2(h);
    __half2 l = __floats2half2_rn(v.x - hf.x, v.y - hf.y);
    hi = *reinterpret_cast<uint32_t*>(&h);
    lo = *reinterpret_cast<uint32_t*>(&l);
}

// mma.sync m16n8k16 row.col f32.f16.f16.f32 (base PTX, works on compute_103)
__device__ __forceinline__ void mma16816h(float c[4], const uint32_t a[4],
                                          uint32_t b0, uint32_t b1) {
    asm volatile(
        "mma.sync.aligned.m16n8k16.row.col.f32.f16.f16.f32 "
        "{%0,%1,%2,%3}, {%4,%5,%6,%7}, {%8,%9}, {%0,%1,%2,%3};"
        : "+f"(c[0]), "+f"(c[1]), "+f"(c[2]), "+f"(c[3])
        : "r"(a[0]), "r"(a[1]), "r"(a[2]), "r"(a[3]), "r"(b0), "r"(b1));
}

// ======================= Kernel 1: gates GEMM on HMMA (fp16 2-term) =======================
// g_xgb[r][g] = sum_k x[r][k]*W[g][k] + b_ih[g] + b_hh[g]
// fp16 2-term: D += Ahi*W16 + Alo*W16   (x = Ahi + Alo exactly to 2^-22; W16 = fp16(W))
// k-PERMUTED fragments: MMA-k {2tig,2tig+1,2tig+8,2tig+9} <- cols {4tig..4tig+3}
// CTA: 256 rows; 8 warps x 32 rows (2 m-tiles of 16); N=32 (4 n-tiles); 16 k-steps.
#define TILE_M 256

__global__ __launch_bounds__(256) void gemm_mma(
    const float* __restrict__ x, const float* __restrict__ W,
    const float* __restrict__ bih, const float* __restrict__ bhh)
{
    // B fragments prepacked (single fp16 term): [ks][nt][lane*2 + reg]
    __shared__ __align__(16) uint32_t bfrag[16][4][64];
    __shared__ float bs[G_DIM];

    const int tid = threadIdx.x;
    if (tid < G_DIM) bs[tid] = bih[tid] + bhh[tid];

    // ---- prepack W (fp32 -> fp16) into PERMUTED B-fragment layout ----
    for (int e = tid; e < 4096; e += 256) {
        const int reg  = e & 1;
        const int lane = (e >> 1) & 31;
        const int nt   = (e >> 6) & 3;
        const int ks   = e >> 8;
        const int n    = nt * 8 + (lane >> 2);
        const int k    = ks * 16 + (lane & 3) * 4 + reg * 2;
        float2 w = *reinterpret_cast<const float2*>(&W[n * D_DIM + k]);
        __half2 wh = __floats2half2_rn(w.x, w.y);
        bfrag[ks][nt][lane * 2 + reg] = *reinterpret_cast<uint32_t*>(&wh);
    }
    __syncthreads();

    const int wid  = tid >> 5;
    const int lane = tid & 31;
    const int g    = lane >> 2;
    const int tig  = lane & 3;
    const long rb  = (long)blockIdx.x * TILE_M + wid * 32;

    const float* xr00 = &x[(rb + g) * D_DIM];        // m-tile 0, row g
    const float* xr01 = &x[(rb + g + 8) * D_DIM];    // m-tile 0, row g+8
    const float* xr10 = &x[(rb + 16 + g) * D_DIM];   // m-tile 1, row g
    const float* xr11 = &x[(rb + 24 + g) * D_DIM];   // m-tile 1, row g+8

    float acc[2][4][4] = {};

#pragma unroll 4
    for (int ks = 0; ks < 16; ks++) {
        const int k0 = ks * 16 + tig * 4;
        const float4 v00 = *reinterpret_cast<const float4*>(&xr00[k0]);
        const float4 v01 = *reinterpret_cast<const float4*>(&xr01[k0]);
        const float4 v10 = *reinterpret_cast<const float4*>(&xr10[k0]);
        const float4 v11 = *reinterpret_cast<const float4*>(&xr11[k0]);

        uint32_t ahi0[4], alo0[4], ahi1[4], alo1[4];
        split2h(make_float2(v00.x, v00.y), ahi0[0], alo0[0]);
        split2h(make_float2(v01.x, v01.y), ahi0[1], alo0[1]);
        split2h(make_float2(v00.z, v00.w), ahi0[2], alo0[2]);
        split2h(make_float2(v01.z, v01.w), ahi0[3], alo0[3]);
        split2h(make_float2(v10.x, v10.y), ahi1[0], alo1[0]);
        split2h(make_float2(v11.x, v11.y), ahi1[1], alo1[1]);
        split2h(make_float2(v10.z, v10.w), ahi1[2], alo1[2]);
        split2h(make_float2(v11.z, v11.w), ahi1[3], alo1[3]);

#pragma unroll
        for (int nt = 0; nt < 4; nt++) {
            const uint2 bh = *reinterpret_cast<const uint2*>(&bfrag[ks][nt][lane * 2]);
            mma16816h(acc[0][nt], ahi0, bh.x, bh.y);
            mma16816h(acc[0][nt], alo0, bh.x, bh.y);
            mma16816h(acc[1][nt], ahi1, bh.x, bh.y);
            mma16816h(acc[1][nt], alo1, bh.x, bh.y);
        }
    }

    // ---- epilogue: c0,c1 -> (row g, col 2tig..+1); c2,c3 -> (row g+8) ----
#pragma unroll
    for (int mt = 0; mt < 2; mt++) {
        const long r0 = rb + mt * 16 + g;
        const long r1 = r0 + 8;
#pragma unroll
        for (int nt = 0; nt < 4; nt++) {
            const int col = nt * 8 + tig * 2;
            const float b0 = bs[col], b1 = bs[col + 1];
            *reinterpret_cast<float2*>(&g_xgb[r0 * G_DIM + col]) =
                make_float2(acc[mt][nt][0] + b0, acc[mt][nt][1] + b1);
            *reinterpret_cast<float2*>(&g_xgb[r1 * G_DIM + col]) =
                make_float2(acc[mt][nt][2] + b0, acc[mt][nt][3] + b1);
        }
    }
}

// ======================= worklist build (with segment length) =======================
__global__ void zero_cnt_kernel() { g_wl_cnt = 0; }

__global__ __launch_bounds__(256) void compact_kernel(const int* __restrict__ reset) {
    const int gid = blockIdx.x * 256 + threadIdx.x;          // gid = t0*256 + b
    const bool start = (gid < M_ROWS) && ((gid >> 8) == 0 || reset[gid] != 0);
    int len = 0;
    if (start) {   // walk to segment end (mean length ~2)
        const int b = gid & 255;
        int tt = (gid >> 8) + 1;
        len = 1;
        while (tt < T_DIM && reset[tt * B_DIM + b] == 0) { len++; tt++; }
    }
    const unsigned bal = __ballot_sync(0xFFFFFFFFu, start);
    if (!bal) return;
    int base = 0;
    if ((threadIdx.x & 31) == 0) base = atomicAdd(&g_wl_cnt, __popc(bal));
    base = __shfl_sync(0xFFFFFFFFu, base, 0);
    if (start) {
        const int rank = __popc(bal & ((1u << (threadIdx.x & 31)) - 1u));
        g_wl[base + rank] = gid | (len << 19);
    }
}

// ======================= Kernel 2: one-thread-per-segment LSTM scan =======================
__device__ __forceinline__ float tanh_mufu(float x) {
    float y;
    asm("tanh.approx.f32 %0, %1;" : "=f"(y) : "f"(x));
    return y;
}
__device__ __forceinline__ float sig_mufu(float x) {
    return fmaf(0.5f, tanh_mufu(0.5f * x), 0.5f);
}

#define SCAN_TPB 128
#define LANES 32768
#define SCAN_BLOCKS (LANES / SCAN_TPB)   // 256

// acc += dot(h[0..7], wsh[base..base+7])  -- uniform LDS.128 broadcast
#define DOT8(acc, base) do {                                                   \
    float4 _wa = *reinterpret_cast<const float4*>(&wsh[(base)]);               \
    float4 _wb = *reinterpret_cast<const float4*>(&wsh[(base) + 4]);           \
    acc = fmaf(h[0], _wa.x, acc); acc = fmaf(h[1], _wa.y, acc);                \
    acc = fmaf(h[2], _wa.z, acc); acc = fmaf(h[3], _wa.w, acc);                \
    acc = fmaf(h[4], _wb.x, acc); acc = fmaf(h[5], _wb.y, acc);                \
    acc = fmaf(h[6], _wb.z, acc); acc = fmaf(h[7], _wb.w, acc);                \
} while (0)

__global__ __launch_bounds__(SCAN_TPB) void scan_kernel(
    const float* __restrict__ Whh,
    const float* __restrict__ Wproj, const float* __restrict__ bproj,
    float* __restrict__ out)
{
    __shared__ __align__(16) float wsh[G_DIM * H_DIM];   // [gate row][k]
    __shared__ float wpsh[H_DIM];
    __shared__ float bpsh;
    const int tid = threadIdx.x;
    wsh[tid] = Whh[tid];
    wsh[tid + 128] = Whh[tid + 128];
    if (tid < H_DIM) wpsh[tid] = Wproj[tid];
    if (tid == 0) bpsh = bproj[0];
    __syncthreads();

    float wp[8];
#pragma unroll
    for (int k = 0; k < 8; k++) wp[k] = wpsh[k];
    const float bp = bpsh;

    const int count = g_wl_cnt;
    int idx = blockIdx.x * SCAN_TPB + tid;

    int next_e = -1;
    if (idx < count) { next_e = g_wl[idx]; idx += LANES; }

    float h[8], cs[8], cg[32];
#pragma unroll
    for (int k = 0; k < 8; k++) { h[k] = 0.0f; cs[k] = 0.0f; }

    int t = 0, b = 0, rem = 0;
    bool active = (next_e >= 0);
    if (active) {
        const int gid = next_e & 0x7FFFF;
        rem = next_e >> 19;
        t = gid >> 8;
        b = gid & 255;
        const float4* rp = reinterpret_cast<const float4*>(&g_xgb[((long)t * B_DIM + b) * G_DIM]);
#pragma unroll
        for (int q = 0; q < 8; q++) *reinterpret_cast<float4*>(&cg[q * 4]) = rp[q];
        next_e = -1;
        if (idx < count) { next_e = g_wl[idx]; idx += LANES; }
    }

    while (active) {   // per-lane independent loop: no warp collectives inside
        // --- decide next row & prefetch it (continuation or next segment start) ---
        const bool more = (rem > 1);
        bool consume = false, nactive;
        int nt, nb, nrem = 0;
        if (more)              { nt = t + 1;  nb = b;  nactive = true; }
        else if (next_e >= 0)  {
            const int gid = next_e & 0x7FFFF;
            nrem = next_e >> 19;
            nt = gid >> 8; nb = gid & 255;
            nactive = true; consume = true;
        } else                 { nt = t; nb = b; nactive = false; }

        float ng[32];
        {
            const float4* rp = reinterpret_cast<const float4*>(&g_xgb[((long)nt * B_DIM + nb) * G_DIM]);
#pragma unroll
            for (int q = 0; q < 8; q++) *reinterpret_cast<float4*>(&ng[q * 4]) = rp[q];
        }

        // --- LSTM cell: all 8 hidden units in this thread ---
        float hn[8];
#pragma unroll
        for (int j = 0; j < 8; j++) {
            float gi = cg[j], gf = cg[8 + j], gg = cg[16 + j], go = cg[24 + j];
            DOT8(gi, j * 8);
            DOT8(gf, (8 + j) * 8);
            DOT8(gg, (16 + j) * 8);
            DOT8(go, (24 + j) * 8);
            const float iv = sig_mufu(gi);
            const float fv = sig_mufu(gf);
            const float gv = tanh_mufu(gg);
            const float ov = sig_mufu(go);
            cs[j] = fmaf(fv, cs[j], iv * gv);
            hn[j] = ov * tanh_mufu(cs[j]);
        }
#pragma unroll
        for (int j = 0; j < 8; j++) h[j] = hn[j];

        float v = bp;
#pragma unroll
        for (int k = 0; k < 8; k++) v = fmaf(h[k], wp[k], v);
        out[t * B_DIM + b] = v;

        // --- advance ---
        if (more) {
            rem--;
        } else {
#pragma unroll
            for (int j = 0; j < 8; j++) { h[j] = 0.0f; cs[j] = 0.0f; }
            rem = nrem;
            if (consume) {
                next_e = -1;
                if (idx < count) { next_e = g_wl[idx]; idx += LANES; }
            }
        }
        t = nt; b = nb;
        active = nactive;
#pragma unroll
        for (int q = 0; q < 32; q++) cg[q] = ng[q];
    }
}

// ======================= launch =======================
extern "C" void kernel_launch(void* const* d_in, const int* in_sizes, int n_in,
                              void* d_out, int out_size) {
    const float* x      = (const float*)d_in[0];
    const int*   reset  = (const int*)d_in[1];
    const float* W_ih   = (const float*)d_in[2];
    const float* W_hh   = (const float*)d_in[3];
    const float* b_ih   = (const float*)d_in[4];
    const float* b_hh   = (const float*)d_in[5];
    const float* W_proj = (const float*)d_in[6];
    const float* b_proj = (const float*)d_in[7];
    float* out = (float*)d_out;

    zero_cnt_kernel<<<1, 1>>>();
    compact_kernel<<<M_ROWS / 256, 256>>>(reset);
    gemm_mma<<<M_ROWS / TILE_M, 256>>>(x, W_ih, b_ih, b_hh);
    scan_kernel<<<SCAN_BLOCKS, SCAN_TPB>>>(W_hh, W_proj, b_proj, out);
}

// round 17
// speedup vs baseline: 2.0915x; 1.0485x over previous
#include <cuda_runtime.h>
#include <cuda_fp16.h>
#include <cstdint>

#define T_DIM 2048
#define B_DIM 256
#define D_DIM 256
#define G_DIM 32               // 4*H
#define H_DIM 8
#define M_ROWS (T_DIM * B_DIM) // 524288

// 64 MB scratch for gate pre-activations (x @ W_ih^T + b_ih + b_hh)
__device__ __align__(16) float g_xgb[(size_t)M_ROWS * G_DIM];
// segment worklist: entry = gid | (len << 19)   (gid < 2^19, len <= 2048)
__device__ int g_wl[M_ROWS];
__device__ int g_wl_cnt;

// ---------------- fp16 split helper: v -> (hi, lo) packed fp16x2 ----------------
__device__ __forceinline__ void split2h(float2 v, uint32_t& hi, uint32_t& lo) {
    __half2 h = __floats2half2_rn(v.x, v.y);
    float2 hf = __half22float2(h);
    __half2 l = __floats2half2_rn(v.x - hf.x, v.y - hf.y);
    hi = *reinterpret_cast<uint32_t*>(&h);
    lo = *reinterpret_cast<uint32_t*>(&l);
}

// mma.sync m16n8k16 row.col f32.f16.f16.f32 (base PTX, works on compute_103)
__device__ __forceinline__ void mma16816h(float c[4], const uint32_t a[4],
                                          uint32_t b0, uint32_t b1) {
    asm volatile(
        "mma.sync.aligned.m16n8k16.row.col.f32.f16.f16.f32 "
        "{%0,%1,%2,%3}, {%4,%5,%6,%7}, {%8,%9}, {%0,%1,%2,%3};"
        : "+f"(c[0]), "+f"(c[1]), "+f"(c[2]), "+f"(c[3])
        : "r"(a[0]), "r"(a[1]), "r"(a[2]), "r"(a[3]), "r"(b0), "r"(b1));
}

// ---------------- cp.async helpers (LDGSTS, base PTX sm_80+) ----------------
__device__ __forceinline__ uint32_t smem_u32(const void* p) {
    uint32_t a;
    asm("{ .reg .u64 t; cvta.to.shared.u64 t, %1; cvt.u32.u64 %0, t; }" : "=r"(a) : "l"(p));
    return a;
}
__device__ __forceinline__ void cp16(uint32_t s, const void* g) {
    asm volatile("cp.async.cg.shared.global [%0], [%1], 16;" :: "r"(s), "l"(g));
}
#define CP_COMMIT() asm volatile("cp.async.commit_group;" ::: "memory")
#define CP_WAIT(n)  asm volatile("cp.async.wait_group %0;" :: "n"(n) : "memory")

// ======================= Kernel 1: gates GEMM on HMMA (cp.async pipeline) ==============
// g_xgb[r][g] = sum_k x[r][k]*W[g][k] + b_ih[g] + b_hh[g]
// fp16 2-term: D += Ahi*W16 + Alo*W16   (x = Ahi + Alo; W16 = fp16(W))
// k-PERMUTED fragments: MMA-k {2tig,2tig+1,2tig+8,2tig+9} <- cols {4tig..4tig+3}
// CTA: 256 rows; 8 warps x 32 rows (2 m-tiles of 16); N=32 (4 n-tiles); 16 k-steps.
// A staged through a 4-deep cp.async pipeline: stage = 256 rows x 16 cols = 16 KB.
#define TILE_M 256
#define NS 4
#define STG_BYTES (TILE_M * 16 * 4)          // 16384
#define SM_XS 0
#define SM_BF (NS * STG_BYTES)               // 65536
#define SM_BS (SM_BF + 16 * 4 * 64 * 4)      // 81920 -> bias at 81920... (bfrag 16KB? no: 16*4*64*4B = 16384)
#define SM_TOTAL (SM_BS + G_DIM * 4)

__global__ __launch_bounds__(256) void gemm_mma(
    const float* __restrict__ x, const float* __restrict__ W,
    const float* __restrict__ bih, const float* __restrict__ bhh)
{
    extern __shared__ __align__(16) char smem[];
    uint32_t* bfrag = reinterpret_cast<uint32_t*>(smem + SM_BF);  // [ks][nt][64]
    float* bs = reinterpret_cast<float*>(smem + SM_BS);

    const int tid = threadIdx.x;
    const long rowBase = (long)blockIdx.x * TILE_M;
    const uint32_t sm_xs = smem_u32(smem);

    // ---- kick off first NS-1 pipeline stages immediately ----
#pragma unroll
    for (int s = 0; s < NS - 1; s++) {
#pragma unroll
        for (int j = 0; j < 4; j++) {
            const int c = tid + j * 256;
            const int row = c >> 2, part = c & 3;
            cp16(sm_xs + s * STG_BYTES + row * 64 + part * 16,
                 &x[(rowBase + row) * D_DIM + s * 16 + part * 4]);
        }
        CP_COMMIT();
    }

    if (tid < G_DIM) bs[tid] = bih[tid] + bhh[tid];

    // ---- prepack W (fp32 -> fp16) into PERMUTED B-fragment layout ----
    for (int e = tid; e < 4096; e += 256) {
        const int reg  = e & 1;
        const int lane = (e >> 1) & 31;
        const int nt   = (e >> 6) & 3;
        const int ks   = e >> 8;
        const int n    = nt * 8 + (lane >> 2);
        const int k    = ks * 16 + (lane & 3) * 4 + reg * 2;
        float2 w = *reinterpret_cast<const float2*>(&W[n * D_DIM + k]);
        __half2 wh = __floats2half2_rn(w.x, w.y);
        bfrag[(ks * 4 + nt) * 64 + lane * 2 + reg] = *reinterpret_cast<uint32_t*>(&wh);
    }
    __syncthreads();

    const int wid  = tid >> 5;
    const int lane = tid & 31;
    const int g    = lane >> 2;
    const int tig  = lane & 3;

    // smem float offsets of this thread's 4 A rows within a stage
    const int fo00 = (wid * 32 + g) * 16 + tig * 4;
    const int fo01 = fo00 + 8 * 16;
    const int fo10 = fo00 + 16 * 16;
    const int fo11 = fo00 + 24 * 16;

    float acc[2][4][4] = {};

    for (int ks = 0; ks < 16; ks++) {
        CP_WAIT(NS - 2);          // stage ks resident
        __syncthreads();

        // refill: stage ks+NS-1 into buffer (ks+NS-1)%NS (that buffer was consumed at iter ks-1)
        const int nxt = ks + NS - 1;
        if (nxt < 16) {
#pragma unroll
            for (int j = 0; j < 4; j++) {
                const int c = tid + j * 256;
                const int row = c >> 2, part = c & 3;
                cp16(sm_xs + (nxt & (NS - 1)) * STG_BYTES + row * 64 + part * 16,
                     &x[(rowBase + row) * D_DIM + nxt * 16 + part * 4]);
            }
        }
        CP_COMMIT();              // always commit (empty groups keep wait count exact)

        const float* xs = reinterpret_cast<const float*>(smem + (ks & (NS - 1)) * STG_BYTES);
        const float4 v00 = *reinterpret_cast<const float4*>(&xs[fo00]);
        const float4 v01 = *reinterpret_cast<const float4*>(&xs[fo01]);
        const float4 v10 = *reinterpret_cast<const float4*>(&xs[fo10]);
        const float4 v11 = *reinterpret_cast<const float4*>(&xs[fo11]);

        uint32_t ahi0[4], alo0[4], ahi1[4], alo1[4];
        split2h(make_float2(v00.x, v00.y), ahi0[0], alo0[0]);
        split2h(make_float2(v01.x, v01.y), ahi0[1], alo0[1]);
        split2h(make_float2(v00.z, v00.w), ahi0[2], alo0[2]);
        split2h(make_float2(v01.z, v01.w), ahi0[3], alo0[3]);
        split2h(make_float2(v10.x, v10.y), ahi1[0], alo1[0]);
        split2h(make_float2(v11.x, v11.y), ahi1[1], alo1[1]);
        split2h(make_float2(v10.z, v10.w), ahi1[2], alo1[2]);
        split2h(make_float2(v11.z, v11.w), ahi1[3], alo1[3]);

#pragma unroll
        for (int nt = 0; nt < 4; nt++) {
            const uint2 bh = *reinterpret_cast<const uint2*>(&bfrag[(ks * 4 + nt) * 64 + lane * 2]);
            mma16816h(acc[0][nt], ahi0, bh.x, bh.y);
            mma16816h(acc[0][nt], alo0, bh.x, bh.y);
            mma16816h(acc[1][nt], ahi1, bh.x, bh.y);
            mma16816h(acc[1][nt], alo1, bh.x, bh.y);
        }
    }

    // ---- epilogue: c0,c1 -> (row g, col 2tig..+1); c2,c3 -> (row g+8) ----
    const long rbw = rowBase + wid * 32;
#pragma unroll
    for (int mt = 0; mt < 2; mt++) {
        const long r0 = rbw + mt * 16 + g;
        const long r1 = r0 + 8;
#pragma unroll
        for (int nt = 0; nt < 4; nt++) {
            const int col = nt * 8 + tig * 2;
            const float b0 = bs[col], b1 = bs[col + 1];
            *reinterpret_cast<float2*>(&g_xgb[r0 * G_DIM + col]) =
                make_float2(acc[mt][nt][0] + b0, acc[mt][nt][1] + b1);
            *reinterpret_cast<float2*>(&g_xgb[r1 * G_DIM + col]) =
                make_float2(acc[mt][nt][2] + b0, acc[mt][nt][3] + b1);
        }
    }
}

// ======================= worklist build (with segment length) =======================
__global__ void zero_cnt_kernel() { g_wl_cnt = 0; }

__global__ __launch_bounds__(256) void compact_kernel(const int* __restrict__ reset) {
    const int gid = blockIdx.x * 256 + threadIdx.x;          // gid = t0*256 + b
    const bool start = (gid < M_ROWS) && ((gid >> 8) == 0 || reset[gid] != 0);
    int len = 0;
    if (start) {   // walk to segment end (mean length ~2)
        const int b = gid & 255;
        int tt = (gid >> 8) + 1;
        len = 1;
        while (tt < T_DIM && reset[tt * B_DIM + b] == 0) { len++; tt++; }
    }
    const unsigned bal = __ballot_sync(0xFFFFFFFFu, start);
    if (!bal) return;
    int base = 0;
    if ((threadIdx.x & 31) == 0) base = atomicAdd(&g_wl_cnt, __popc(bal));
    base = __shfl_sync(0xFFFFFFFFu, base, 0);
    if (start) {
        const int rank = __popc(bal & ((1u << (threadIdx.x & 31)) - 1u));
        g_wl[base + rank] = gid | (len << 19);
    }
}

// ======================= Kernel 2: one-thread-per-segment LSTM scan =======================
__device__ __forceinline__ float tanh_mufu(float x) {
    float y;
    asm("tanh.approx.f32 %0, %1;" : "=f"(y) : "f"(x));
    return y;
}
__device__ __forceinline__ float sig_mufu(float x) {
    return fmaf(0.5f, tanh_mufu(0.5f * x), 0.5f);
}

#define SCAN_TPB 128
#define LANES 32768
#define SCAN_BLOCKS (LANES / SCAN_TPB)   // 256

// acc += dot(h[0..7], wsh[base..base+7])  -- uniform LDS.128 broadcast
#define DOT8(acc, base) do {                                                   \
    float4 _wa = *reinterpret_cast<const float4*>(&wsh[(base)]);               \
    float4 _wb = *reinterpret_cast<const float4*>(&wsh[(base) + 4]);           \
    acc = fmaf(h[0], _wa.x, acc); acc = fmaf(h[1], _wa.y, acc);                \
    acc = fmaf(h[2], _wa.z, acc); acc = fmaf(h[3], _wa.w, acc);                \
    acc = fmaf(h[4], _wb.x, acc); acc = fmaf(h[5], _wb.y, acc);                \
    acc = fmaf(h[6], _wb.z, acc); acc = fmaf(h[7], _wb.w, acc);                \
} while (0)

__global__ __launch_bounds__(SCAN_TPB) void scan_kernel(
    const float* __restrict__ Whh,
    const float* __restrict__ Wproj, const float* __restrict__ bproj,
    float* __restrict__ out)
{
    __shared__ __align__(16) float wsh[G_DIM * H_DIM];   // [gate row][k]
    __shared__ float wpsh[H_DIM];
    __shared__ float bpsh;
    const int tid = threadIdx.x;
    wsh[tid] = Whh[tid];
    wsh[tid + 128] = Whh[tid + 128];
    if (tid < H_DIM) wpsh[tid] = Wproj[tid];
    if (tid == 0) bpsh = bproj[0];
    __syncthreads();

    float wp[8];
#pragma unroll
    for (int k = 0; k < 8; k++) wp[k] = wpsh[k];
    const float bp = bpsh;

    const int count = g_wl_cnt;
    int idx = blockIdx.x * SCAN_TPB + tid;

    int next_e = -1;
    if (idx < count) { next_e = g_wl[idx]; idx += LANES; }

    float h[8], cs[8], cg[32];
#pragma unroll
    for (int k = 0; k < 8; k++) { h[k] = 0.0f; cs[k] = 0.0f; }

    int t = 0, b = 0, rem = 0;
    bool active = (next_e >= 0);
    if (active) {
        const int gid = next_e & 0x7FFFF;
        rem = next_e >> 19;
        t = gid >> 8;
        b = gid & 255;
        const float4* rp = reinterpret_cast<const float4*>(&g_xgb[((long)t * B_DIM + b) * G_DIM]);
#pragma unroll
        for (int q = 0; q < 8; q++) *reinterpret_cast<float4*>(&cg[q * 4]) = rp[q];
        next_e = -1;
        if (idx < count) { next_e = g_wl[idx]; idx += LANES; }
    }

    while (active) {   // per-lane independent loop: no warp collectives inside
        // --- decide next row & prefetch it (continuation or next segment start) ---
        const bool more = (rem > 1);
        bool consume = false, nactive;
        int nt, nb, nrem = 0;
        if (more)              { nt = t + 1;  nb = b;  nactive = true; }
        else if (next_e >= 0)  {
            const int gid = next_e & 0x7FFFF;
            nrem = next_e >> 19;
            nt = gid >> 8; nb = gid & 255;
            nactive = true; consume = true;
        } else                 { nt = t; nb = b; nactive = false; }

        float ng[32];
        {
            const float4* rp = reinterpret_cast<const float4*>(&g_xgb[((long)nt * B_DIM + nb) * G_DIM]);
#pragma unroll
            for (int q = 0; q < 8; q++) *reinterpret_cast<float4*>(&ng[q * 4]) = rp[q];
        }

        // --- LSTM cell: all 8 hidden units in this thread ---
        float hn[8];
#pragma unroll
        for (int j = 0; j < 8; j++) {
            float gi = cg[j], gf = cg[8 + j], gg = cg[16 + j], go = cg[24 + j];
            DOT8(gi, j * 8);
            DOT8(gf, (8 + j) * 8);
            DOT8(gg, (16 + j) * 8);
            DOT8(go, (24 + j) * 8);
            const float iv = sig_mufu(gi);
            const float fv = sig_mufu(gf);
            const float gv = tanh_mufu(gg);
            const float ov = sig_mufu(go);
            cs[j] = fmaf(fv, cs[j], iv * gv);
            hn[j] = ov * tanh_mufu(cs[j]);
        }
#pragma unroll
        for (int j = 0; j < 8; j++) h[j] = hn[j];

        float v = bp;
#pragma unroll
        for (int k = 0; k < 8; k++) v = fmaf(h[k], wp[k], v);
        out[t * B_DIM + b] = v;

        // --- advance ---
        if (more) {
            rem--;
        } else {
#pragma unroll
            for (int j = 0; j < 8; j++) { h[j] = 0.0f; cs[j] = 0.0f; }
            rem = nrem;
            if (consume) {
                next_e = -1;
                if (idx < count) { next_e = g_wl[idx]; idx += LANES; }
            }
        }
        t = nt; b = nb;
        active = nactive;
#pragma unroll
        for (int q = 0; q < 32; q++) cg[q] = ng[q];
    }
}

// ======================= launch =======================
extern "C" void kernel_launch(void* const* d_in, const int* in_sizes, int n_in,
                              void* d_out, int out_size) {
    const float* x      = (const float*)d_in[0];
    const int*   reset  = (const int*)d_in[1];
    const float* W_ih   = (const float*)d_in[2];
    const float* W_hh   = (const float*)d_in[3];
    const float* b_ih   = (const float*)d_in[4];
    const float* b_hh   = (const float*)d_in[5];
    const float* W_proj = (const float*)d_in[6];
    const float* b_proj = (const float*)d_in[7];
    float* out = (float*)d_out;

    static int smem_set = 0;
    if (!smem_set) {
        cudaFuncSetAttribute(gemm_mma, cudaFuncAttributeMaxDynamicSharedMemorySize, SM_TOTAL);
        smem_set = 1;
    }

    zero_cnt_kernel<<<1, 1>>>();
    compact_kernel<<<M_ROWS / 256, 256>>>(reset);
    gemm_mma<<<M_ROWS / TILE_M, 256, SM_TOTAL>>>(x, W_ih, b_ih, b_hh);
    scan_kernel<<<SCAN_BLOCKS, SCAN_TPB>>>(W_hh, W_proj, b_proj, out);
}